// round 6
// baseline (speedup 1.0000x reference)
#include <cuda_runtime.h>
#include <math.h>

#define B_  32
#define C_  3
#define H_  480
#define W_  480
#define AH  30
#define AW  30
#define PAD 48          // int(0.1 * 480)

#define ROW_TILES 30
#define ROWS_PER_TILE 16

#define BROWS 16        // rows per blend block
#define QW   (W_ / 4)   // 120 float4 pixels per row
#define CH_STRIDE (H_ * W_)

// Encoded bbox accumulators, zero-init == "empty mask" defaults.
// [0] = H - minh, [1] = maxh + 1, [2] = W - minw, [3] = maxw + 1.
// atomicMax-combined -> idempotent across graph replays.
__device__ int g_enc[B_][4];

// ---------------------------------------------------------------------------
// Kernel A: theta + mask tile + bbox atomics. grid=(ROW_TILES, B_), 256 thr.
// ---------------------------------------------------------------------------
__global__ void __launch_bounds__(256) bbox_kernel(const float* __restrict__ atten) {
    const int b    = blockIdx.y;
    const int tile = blockIdx.x;
    const int tid  = threadIdx.x;

    __shared__ float s_att[AH * AW];
    __shared__ float s_wmax[8];
    __shared__ int s_minh, s_maxh, s_minw, s_maxw;

    const float* a = atten + b * (AH * AW);
    float m = -1e30f;
    for (int i = tid; i < AH * AW; i += 256) {
        float v = a[i];
        s_att[i] = v;
        m = fmaxf(m, v);
    }
    // warp-shuffle max reduce
#pragma unroll
    for (int s = 16; s > 0; s >>= 1)
        m = fmaxf(m, __shfl_xor_sync(0xffffffffu, m, s));
    if ((tid & 31) == 0) s_wmax[tid >> 5] = m;
    if (tid == 0) { s_minh = H_; s_maxh = -1; s_minw = W_; s_maxw = -1; }
    __syncthreads();
    float mm = fmaxf(fmaxf(fmaxf(s_wmax[0], s_wmax[1]), fmaxf(s_wmax[2], s_wmax[3])),
                     fmaxf(fmaxf(s_wmax[4], s_wmax[5]), fmaxf(s_wmax[6], s_wmax[7])));
    const float theta = 0.5f * mm;

    int minh = H_, maxh = -1, minw = W_, maxw = -1;

    const int h_start = tile * ROWS_PER_TILE;
#pragma unroll 1
    for (int h = h_start; h < h_start + ROWS_PER_TILE; ++h) {
        float sy = (h + 0.5f) * 0.0625f - 0.5f;
        sy = fminf(fmaxf(sy, 0.0f), (float)(AH - 1));
        const int   y0 = (int)sy;
        const float wy = sy - (float)y0;
        const int   y1 = min(y0 + 1, AH - 1);
        const float* r0p = s_att + y0 * AW;
        const float* r1p = s_att + y1 * AW;

#pragma unroll 1
        for (int w = tid; w < W_; w += 256) {
            float sx = (w + 0.5f) * 0.0625f - 0.5f;
            sx = fminf(fmaxf(sx, 0.0f), (float)(AW - 1));
            const int   x0 = (int)sx;
            const float wx = sx - (float)x0;
            const int   x1 = min(x0 + 1, AW - 1);

            const float ra = r0p[x0] * (1.0f - wy) + r1p[x0] * wy;
            const float rb = r0p[x1] * (1.0f - wy) + r1p[x1] * wy;
            const float up = ra * (1.0f - wx) + rb * wx;

            if (up >= theta) {
                minh = min(minh, h); maxh = max(maxh, h);
                minw = min(minw, w); maxw = max(maxw, w);
            }
        }
    }

    atomicMin(&s_minh, minh); atomicMax(&s_maxh, maxh);
    atomicMin(&s_minw, minw); atomicMax(&s_maxw, maxw);
    __syncthreads();

    if (tid == 0 && s_maxh >= 0) {
        atomicMax(&g_enc[b][0], H_ - s_minh);
        atomicMax(&g_enc[b][1], s_maxh + 1);
        atomicMax(&g_enc[b][2], W_ - s_minw);
        atomicMax(&g_enc[b][3], s_maxw + 1);
    }
}

// ---------------------------------------------------------------------------
// Kernel B: fused crop-resize + mixup blend, ALL 3 CHANNELS per block.
// One block per (b, 16-row group); 128 threads; 1 barrier per row-triple.
// ---------------------------------------------------------------------------
__global__ void __launch_bounds__(128) blend_kernel(const float* __restrict__ images,
                                                    float* __restrict__ out) {
    const int ngroups = H_ / BROWS;             // 30
    const int b      = blockIdx.x / ngroups;
    const int y_base = (blockIdx.x - b * ngroups) * BROWS;
    const int tid    = threadIdx.x;

    __shared__ __align__(16) float s_row[2][C_][484];

    // decode + pad + clamp bbox (once per block)
    const int minh = H_ - g_enc[b][0];
    const int maxh = g_enc[b][1] - 1;
    const int minw = W_ - g_enc[b][2];
    const int maxw = g_enc[b][3] - 1;
    const int h0 = max(minh - PAD, 0);
    const int h1 = min(maxh + PAD, H_);
    const int w0 = max(minw - PAD, 0);
    const int w1 = min(maxw + PAD, W_);

    const int   crop_h = h1 - h0;
    const int   crop_w = w1 - w0;
    const float chf = (float)crop_h;
    const float cwf = (float)crop_w;
    const float sy_scale = chf * (1.0f / (float)H_);
    const float sx_scale = cwf * (1.0f / (float)W_);

    const int w0a = w0 & ~3;                    // float4-aligned window start
    const int off = w0 - w0a;
    const int nq  = ((w1 - w0a) + 3) >> 2;      // quads to fill (<= 121)

    // per-thread x-mapping, computed ONCE, reused for all rows & channels
    int   fxa[4], fxb[4];
    float wxv[4];
    const int x_base = tid * 4;
    if (tid < QW) {
#pragma unroll
        for (int k = 0; k < 4; ++k) {
            float sx = ((float)(x_base + k) + 0.5f) * sx_scale - 0.5f;
            sx = fminf(fmaxf(sx, 0.0f), cwf - 1.0f);
            const int fx0 = (int)sx;
            wxv[k] = sx - (float)fx0;
            fxa[k] = off + fx0;
            fxb[k] = off + min(fx0 + 1, crop_w - 1);
        }
    }

    const float* __restrict__ img0 = images + (size_t)b * (C_ * CH_STRIDE);
    float* __restrict__ out0       = out    + (size_t)b * (C_ * CH_STRIDE);

#pragma unroll 1
    for (int r = 0; r < BROWS; ++r) {
        const int y = y_base + r;
        float (*buf)[484] = s_row[r & 1];

        // block-constant y mapping
        float sy = ((float)y + 0.5f) * sy_scale - 0.5f;
        sy = fminf(fmaxf(sy, 0.0f), chf - 1.0f);
        const int   fy0  = (int)sy;
        const float wy   = sy - (float)fy0;
        const float omwy = 1.0f - wy;
        const size_t r0  = (size_t)(h0 + fy0) * W_ + w0a;
        const size_t r1  = (size_t)(h0 + min(fy0 + 1, crop_h - 1)) * W_ + w0a;

        // cooperative fill: 3 channels x 2 source rows (6 LDG.128 in flight)
        if (tid < nq) {
#pragma unroll
            for (int c = 0; c < C_; ++c) {
                const float* ch = img0 + c * CH_STRIDE;
                const float4 a0 = *reinterpret_cast<const float4*>(ch + r0 + 4 * tid);
                const float4 a1 = *reinterpret_cast<const float4*>(ch + r1 + 4 * tid);
                float4 v;
                v.x = a0.x * omwy + a1.x * wy;
                v.y = a0.y * omwy + a1.y * wy;
                v.z = a0.z * omwy + a1.z * wy;
                v.w = a0.w * omwy + a1.w * wy;
                *reinterpret_cast<float4*>(&buf[c][4 * tid]) = v;
            }
        }

        // identity pixels, 3 channels
        float4 idv[C_];
        if (tid < QW) {
#pragma unroll
            for (int c = 0; c < C_; ++c)
                idv[c] = *reinterpret_cast<const float4*>(img0 + c * CH_STRIDE + (size_t)y * W_ + x_base);
        }

        __syncthreads();        // single barrier per row-triple (double-buffered)

        if (tid < QW) {
#pragma unroll
            for (int c = 0; c < C_; ++c) {
                const float* bc = buf[c];
                float4 o;
                o.x = idv[c].x * 0.6f + 0.4f * (bc[fxa[0]] * (1.0f - wxv[0]) + bc[fxb[0]] * wxv[0]);
                o.y = idv[c].y * 0.6f + 0.4f * (bc[fxa[1]] * (1.0f - wxv[1]) + bc[fxb[1]] * wxv[1]);
                o.z = idv[c].z * 0.6f + 0.4f * (bc[fxa[2]] * (1.0f - wxv[2]) + bc[fxb[2]] * wxv[2]);
                o.w = idv[c].w * 0.6f + 0.4f * (bc[fxa[3]] * (1.0f - wxv[3]) + bc[fxb[3]] * wxv[3]);
                *reinterpret_cast<float4*>(out0 + c * CH_STRIDE + (size_t)y * W_ + x_base) = o;
            }
        }
    }
}

// ---------------------------------------------------------------------------
extern "C" void kernel_launch(void* const* d_in, const int* in_sizes, int n_in,
                              void* d_out, int out_size) {
    const float* images = (const float*)d_in[0];
    const float* atten  = (const float*)d_in[1];
    float* out = (float*)d_out;

    bbox_kernel<<<dim3(ROW_TILES, B_), 256>>>(atten);
    blend_kernel<<<B_ * (H_ / BROWS), 128>>>(images, out);
}

// round 7
// speedup vs baseline: 1.0035x; 1.0035x over previous
#include <cuda_runtime.h>
#include <math.h>

#define B_  32
#define C_  3
#define H_  480
#define W_  480
#define AH  30
#define AW  30
#define PAD 48          // int(0.1 * 480)

#define ROW_TILES 30
#define ROWS_PER_TILE 16

#define BROWS 16        // rows per blend block
#define QW   (W_ / 4)   // 120 float4 pixels per row

// Encoded bbox accumulators, zero-init == "empty mask" defaults.
// [0] = H - minh, [1] = maxh + 1, [2] = W - minw, [3] = maxw + 1.
// atomicMax-combined -> idempotent across graph replays.
__device__ int g_enc[B_][4];

// ---------------------------------------------------------------------------
// Kernel A: theta + mask tile + bbox atomics. grid=(ROW_TILES, B_), 256 thr.
// ---------------------------------------------------------------------------
__global__ void __launch_bounds__(256) bbox_kernel(const float* __restrict__ atten) {
    const int b    = blockIdx.y;
    const int tile = blockIdx.x;
    const int tid  = threadIdx.x;

    __shared__ float s_att[AH * AW];
    __shared__ float s_wmax[8];
    __shared__ int s_minh, s_maxh, s_minw, s_maxw;

    const float* a = atten + b * (AH * AW);
    float m = -1e30f;
    for (int i = tid; i < AH * AW; i += 256) {
        float v = a[i];
        s_att[i] = v;
        m = fmaxf(m, v);
    }
#pragma unroll
    for (int s = 16; s > 0; s >>= 1)
        m = fmaxf(m, __shfl_xor_sync(0xffffffffu, m, s));
    if ((tid & 31) == 0) s_wmax[tid >> 5] = m;
    if (tid == 0) { s_minh = H_; s_maxh = -1; s_minw = W_; s_maxw = -1; }
    __syncthreads();
    float mm = fmaxf(fmaxf(fmaxf(s_wmax[0], s_wmax[1]), fmaxf(s_wmax[2], s_wmax[3])),
                     fmaxf(fmaxf(s_wmax[4], s_wmax[5]), fmaxf(s_wmax[6], s_wmax[7])));
    const float theta = 0.5f * mm;

    int minh = H_, maxh = -1, minw = W_, maxw = -1;

    const int h_start = tile * ROWS_PER_TILE;
#pragma unroll 1
    for (int h = h_start; h < h_start + ROWS_PER_TILE; ++h) {
        float sy = (h + 0.5f) * 0.0625f - 0.5f;
        sy = fminf(fmaxf(sy, 0.0f), (float)(AH - 1));
        const int   y0 = (int)sy;
        const float wy = sy - (float)y0;
        const int   y1 = min(y0 + 1, AH - 1);
        const float* r0p = s_att + y0 * AW;
        const float* r1p = s_att + y1 * AW;

#pragma unroll 1
        for (int w = tid; w < W_; w += 256) {
            float sx = (w + 0.5f) * 0.0625f - 0.5f;
            sx = fminf(fmaxf(sx, 0.0f), (float)(AW - 1));
            const int   x0 = (int)sx;
            const float wx = sx - (float)x0;
            const int   x1 = min(x0 + 1, AW - 1);

            const float ra = r0p[x0] * (1.0f - wy) + r1p[x0] * wy;
            const float rb = r0p[x1] * (1.0f - wy) + r1p[x1] * wy;
            const float up = ra * (1.0f - wx) + rb * wx;

            if (up >= theta) {
                minh = min(minh, h); maxh = max(maxh, h);
                minw = min(minw, w); maxw = max(maxw, w);
            }
        }
    }

    atomicMin(&s_minh, minh); atomicMax(&s_maxh, maxh);
    atomicMin(&s_minw, minw); atomicMax(&s_maxw, maxw);
    __syncthreads();

    if (tid == 0 && s_maxh >= 0) {
        atomicMax(&g_enc[b][0], H_ - s_minh);
        atomicMax(&g_enc[b][1], s_maxh + 1);
        atomicMax(&g_enc[b][2], W_ - s_minw);
        atomicMax(&g_enc[b][3], s_maxw + 1);
    }

    // PDL: allow the dependent blend grid to start; prior writes are visible
    // to dependent threads after their griddepcontrol.wait.
    asm volatile("griddepcontrol.launch_dependents;" ::: "memory");
}

// ---------------------------------------------------------------------------
// Kernel B: fused crop-resize + mixup blend, software-pipelined.
// One block per (b, c, 16-row group); 128 threads; prefetch row r+1's
// global loads before the barrier for row r.
// ---------------------------------------------------------------------------
__global__ void __launch_bounds__(128) blend_kernel(const float* __restrict__ images,
                                                    float* __restrict__ out) {
    const int blk = blockIdx.x;                 // (b, c, rowgroup)
    const int ngroups = H_ / BROWS;             // 30
    const int b   = blk / (C_ * ngroups);
    const int rem = blk - b * (C_ * ngroups);
    const int c   = rem / ngroups;
    const int y_base = (rem - c * ngroups) * BROWS;
    const int tid = threadIdx.x;

    __shared__ __align__(16) float s_row[2][484];

    // PDL: wait for bbox grid's writes to g_enc.
    asm volatile("griddepcontrol.wait;" ::: "memory");

    // decode + pad + clamp bbox (once per block)
    const int minh = H_ - g_enc[b][0];
    const int maxh = g_enc[b][1] - 1;
    const int minw = W_ - g_enc[b][2];
    const int maxw = g_enc[b][3] - 1;
    const int h0 = max(minh - PAD, 0);
    const int h1 = min(maxh + PAD, H_);
    const int w0 = max(minw - PAD, 0);
    const int w1 = min(maxw + PAD, W_);

    const int   crop_h = h1 - h0;
    const int   crop_w = w1 - w0;
    const float chf = (float)crop_h;
    const float cwf = (float)crop_w;
    const float sy_scale = chf * (1.0f / (float)H_);
    const float sx_scale = cwf * (1.0f / (float)W_);

    const int w0a = w0 & ~3;                    // float4-aligned window start
    const int off = w0 - w0a;
    const int nq  = ((w1 - w0a) + 3) >> 2;      // quads to fill (<= 121)

    // per-thread x-mapping, computed once
    int   fxa[4], fxb[4];
    float wxv[4];
    const int x_base = tid * 4;
    if (tid < QW) {
#pragma unroll
        for (int k = 0; k < 4; ++k) {
            float sx = ((float)(x_base + k) + 0.5f) * sx_scale - 0.5f;
            sx = fminf(fmaxf(sx, 0.0f), cwf - 1.0f);
            const int fx0 = (int)sx;
            wxv[k] = sx - (float)fx0;
            fxa[k] = off + fx0;
            fxb[k] = off + min(fx0 + 1, crop_w - 1);
        }
    }

    const float* __restrict__ imgc = images + ((size_t)(b * C_ + c)) * (H_ * W_);
    float* __restrict__ outc       = out    + ((size_t)(b * C_ + c)) * (H_ * W_);

    // ---- software pipeline: prologue loads row 0 ----
    float4 f0, f1, idv;
    float  wy_c;
    {
        const int y = y_base;
        float sy = ((float)y + 0.5f) * sy_scale - 0.5f;
        sy = fminf(fmaxf(sy, 0.0f), chf - 1.0f);
        const int fy0 = (int)sy;
        wy_c = sy - (float)fy0;
        const size_t r0 = (size_t)(h0 + fy0) * W_ + w0a;
        const size_t r1 = (size_t)(h0 + min(fy0 + 1, crop_h - 1)) * W_ + w0a;
        if (tid < nq) {
            f0 = *reinterpret_cast<const float4*>(imgc + r0 + 4 * tid);
            f1 = *reinterpret_cast<const float4*>(imgc + r1 + 4 * tid);
        }
        if (tid < QW)
            idv = *reinterpret_cast<const float4*>(imgc + (size_t)y * W_ + x_base);
    }

#pragma unroll 1
    for (int r = 0; r < BROWS; ++r) {
        float* buf = s_row[r & 1];

        // write y-lerped row r into smem
        if (tid < nq) {
            const float omwy = 1.0f - wy_c;
            float4 v;
            v.x = f0.x * omwy + f1.x * wy_c;
            v.y = f0.y * omwy + f1.y * wy_c;
            v.z = f0.z * omwy + f1.z * wy_c;
            v.w = f0.w * omwy + f1.w * wy_c;
            *reinterpret_cast<float4*>(&buf[4 * tid]) = v;
        }

        // prefetch row r+1 (overlaps barrier + compute below)
        float4 n0, n1, nid;
        float  wy_n = 0.0f;
        if (r + 1 < BROWS) {
            const int y = y_base + r + 1;
            float sy = ((float)y + 0.5f) * sy_scale - 0.5f;
            sy = fminf(fmaxf(sy, 0.0f), chf - 1.0f);
            const int fy0 = (int)sy;
            wy_n = sy - (float)fy0;
            const size_t r0 = (size_t)(h0 + fy0) * W_ + w0a;
            const size_t r1 = (size_t)(h0 + min(fy0 + 1, crop_h - 1)) * W_ + w0a;
            if (tid < nq) {
                n0 = *reinterpret_cast<const float4*>(imgc + r0 + 4 * tid);
                n1 = *reinterpret_cast<const float4*>(imgc + r1 + 4 * tid);
            }
            if (tid < QW)
                nid = *reinterpret_cast<const float4*>(imgc + (size_t)y * W_ + x_base);
        }

        __syncthreads();        // one barrier per row (double-buffered smem)

        // compute + store row r
        if (tid < QW) {
            const int y = y_base + r;
            float4 o;
            o.x = idv.x * 0.6f + 0.4f * (buf[fxa[0]] * (1.0f - wxv[0]) + buf[fxb[0]] * wxv[0]);
            o.y = idv.y * 0.6f + 0.4f * (buf[fxa[1]] * (1.0f - wxv[1]) + buf[fxb[1]] * wxv[1]);
            o.z = idv.z * 0.6f + 0.4f * (buf[fxa[2]] * (1.0f - wxv[2]) + buf[fxb[2]] * wxv[2]);
            o.w = idv.w * 0.6f + 0.4f * (buf[fxa[3]] * (1.0f - wxv[3]) + buf[fxb[3]] * wxv[3]);
            *reinterpret_cast<float4*>(outc + (size_t)y * W_ + x_base) = o;
        }

        f0 = n0; f1 = n1; idv = nid; wy_c = wy_n;
    }
}

// ---------------------------------------------------------------------------
extern "C" void kernel_launch(void* const* d_in, const int* in_sizes, int n_in,
                              void* d_out, int out_size) {
    const float* images = (const float*)d_in[0];
    const float* atten  = (const float*)d_in[1];
    float* out = (float*)d_out;

    bbox_kernel<<<dim3(ROW_TILES, B_), 256>>>(atten);

    // blend with PDL (programmatic stream serialization) so it can begin
    // launching while bbox drains; it waits on griddepcontrol.wait.
    cudaLaunchConfig_t cfg = {};
    cfg.gridDim  = dim3(B_ * C_ * (H_ / BROWS));
    cfg.blockDim = dim3(128);
    cfg.dynamicSmemBytes = 0;
    cfg.stream = 0;
    cudaLaunchAttribute attrs[1];
    attrs[0].id = cudaLaunchAttributeProgrammaticStreamSerialization;
    attrs[0].val.programmaticStreamSerializationAllowed = 1;
    cfg.attrs = attrs;
    cfg.numAttrs = 1;
    cudaLaunchKernelEx(&cfg, blend_kernel, images, out);
}

// round 11
// speedup vs baseline: 1.0670x; 1.0633x over previous
#include <cuda_runtime.h>
#include <math.h>

#define B_  32
#define C_  3
#define H_  480
#define W_  480
#define AH  30
#define AW  30
#define PAD 48          // int(0.1 * 480)

#define ROW_TILES 30
#define ROWS_PER_TILE 16

#define BROWS 30        // rows per blend block -> 16 groups -> 1536 blocks (1 wave)
#define NGROUPS (H_ / BROWS)
#define QW   (W_ / 4)   // 120 float4 pixels per row

// Encoded bbox accumulators, zero-init == "empty mask" defaults.
// [0] = H - minh, [1] = maxh + 1, [2] = W - minw, [3] = maxw + 1.
// atomicMax-combined -> idempotent across graph replays.
__device__ int g_enc[B_][4];

// ---------------------------------------------------------------------------
// Kernel A: theta + mask tile + bbox atomics. grid=(ROW_TILES, B_), 256 thr.
// ---------------------------------------------------------------------------
__global__ void __launch_bounds__(256) bbox_kernel(const float* __restrict__ atten) {
    const int b    = blockIdx.y;
    const int tile = blockIdx.x;
    const int tid  = threadIdx.x;

    __shared__ float s_att[AH * AW];
    __shared__ float s_wmax[8];
    __shared__ int s_minh, s_maxh, s_minw, s_maxw;

    const float* a = atten + b * (AH * AW);
    float m = -1e30f;
    for (int i = tid; i < AH * AW; i += 256) {
        float v = a[i];
        s_att[i] = v;
        m = fmaxf(m, v);
    }
#pragma unroll
    for (int s = 16; s > 0; s >>= 1)
        m = fmaxf(m, __shfl_xor_sync(0xffffffffu, m, s));
    if ((tid & 31) == 0) s_wmax[tid >> 5] = m;
    if (tid == 0) { s_minh = H_; s_maxh = -1; s_minw = W_; s_maxw = -1; }
    __syncthreads();
    float mm = fmaxf(fmaxf(fmaxf(s_wmax[0], s_wmax[1]), fmaxf(s_wmax[2], s_wmax[3])),
                     fmaxf(fmaxf(s_wmax[4], s_wmax[5]), fmaxf(s_wmax[6], s_wmax[7])));
    const float theta = 0.5f * mm;

    int minh = H_, maxh = -1, minw = W_, maxw = -1;

    const int h_start = tile * ROWS_PER_TILE;
#pragma unroll 1
    for (int h = h_start; h < h_start + ROWS_PER_TILE; ++h) {
        float sy = (h + 0.5f) * 0.0625f - 0.5f;
        sy = fminf(fmaxf(sy, 0.0f), (float)(AH - 1));
        const int   y0 = (int)sy;
        const float wy = sy - (float)y0;
        const int   y1 = min(y0 + 1, AH - 1);
        const float* r0p = s_att + y0 * AW;
        const float* r1p = s_att + y1 * AW;

#pragma unroll 1
        for (int w = tid; w < W_; w += 256) {
            float sx = (w + 0.5f) * 0.0625f - 0.5f;
            sx = fminf(fmaxf(sx, 0.0f), (float)(AW - 1));
            const int   x0 = (int)sx;
            const float wx = sx - (float)x0;
            const int   x1 = min(x0 + 1, AW - 1);

            const float ra = r0p[x0] * (1.0f - wy) + r1p[x0] * wy;
            const float rb = r0p[x1] * (1.0f - wy) + r1p[x1] * wy;
            const float up = ra * (1.0f - wx) + rb * wx;

            if (up >= theta) {
                minh = min(minh, h); maxh = max(maxh, h);
                minw = min(minw, w); maxw = max(maxw, w);
            }
        }
    }

    atomicMin(&s_minh, minh); atomicMax(&s_maxh, maxh);
    atomicMin(&s_minw, minw); atomicMax(&s_maxw, maxw);
    __syncthreads();

    if (tid == 0 && s_maxh >= 0) {
        atomicMax(&g_enc[b][0], H_ - s_minh);
        atomicMax(&g_enc[b][1], s_maxh + 1);
        atomicMax(&g_enc[b][2], W_ - s_minw);
        atomicMax(&g_enc[b][3], s_maxw + 1);
    }

    asm volatile("griddepcontrol.launch_dependents;" ::: "memory");
}

// ---------------------------------------------------------------------------
// Kernel B: fused crop-resize + mixup blend (R5 body, 30 rows per block).
// One block per (b, c, 30-row group); 128 threads; 1536 blocks = single wave.
// ---------------------------------------------------------------------------
__global__ void __launch_bounds__(128) blend_kernel(const float* __restrict__ images,
                                                    float* __restrict__ out) {
    const int blk = blockIdx.x;                 // (b, c, rowgroup)
    const int b   = blk / (C_ * NGROUPS);
    const int rem = blk - b * (C_ * NGROUPS);
    const int c   = rem / NGROUPS;
    const int y_base = (rem - c * NGROUPS) * BROWS;
    const int tid = threadIdx.x;

    __shared__ __align__(16) float s_row[2][484];

    asm volatile("griddepcontrol.wait;" ::: "memory");

    // decode + pad + clamp bbox (once per block)
    const int minh = H_ - g_enc[b][0];
    const int maxh = g_enc[b][1] - 1;
    const int minw = W_ - g_enc[b][2];
    const int maxw = g_enc[b][3] - 1;
    const int h0 = max(minh - PAD, 0);
    const int h1 = min(maxh + PAD, H_);
    const int w0 = max(minw - PAD, 0);
    const int w1 = min(maxw + PAD, W_);

    const int   crop_h = h1 - h0;
    const int   crop_w = w1 - w0;
    const float chf = (float)crop_h;
    const float cwf = (float)crop_w;
    const float sy_scale = chf * (1.0f / (float)H_);
    const float sx_scale = cwf * (1.0f / (float)W_);

    const int w0a = w0 & ~3;                    // float4-aligned window start
    const int off = w0 - w0a;
    const int nq  = ((w1 - w0a) + 3) >> 2;      // quads to fill (<= 121)

    // per-thread x-mapping, computed ONCE, reused for all 30 rows
    int   fxa[4], fxb[4];
    float wxv[4];
    const int x_base = tid * 4;
    if (tid < QW) {
#pragma unroll
        for (int k = 0; k < 4; ++k) {
            float sx = ((float)(x_base + k) + 0.5f) * sx_scale - 0.5f;
            sx = fminf(fmaxf(sx, 0.0f), cwf - 1.0f);
            const int fx0 = (int)sx;
            wxv[k] = sx - (float)fx0;
            fxa[k] = off + fx0;
            fxb[k] = off + min(fx0 + 1, crop_w - 1);
        }
    }

    const float* __restrict__ imgc = images + ((size_t)(b * C_ + c)) * (H_ * W_);
    float* __restrict__ outc       = out    + ((size_t)(b * C_ + c)) * (H_ * W_);

#pragma unroll 1
    for (int r = 0; r < BROWS; ++r) {
        const int y = y_base + r;
        float* buf = s_row[r & 1];

        // block-constant y mapping
        float sy = ((float)y + 0.5f) * sy_scale - 0.5f;
        sy = fminf(fmaxf(sy, 0.0f), chf - 1.0f);
        const int   fy0  = (int)sy;
        const float wy   = sy - (float)fy0;
        const float omwy = 1.0f - wy;
        const size_t r0  = (size_t)(h0 + fy0) * W_ + w0a;
        const size_t r1  = (size_t)(h0 + min(fy0 + 1, crop_h - 1)) * W_ + w0a;

        // cooperative vectorized y-lerp fill (one quad per thread)
        if (tid < nq) {
            const float4 a0 = *reinterpret_cast<const float4*>(imgc + r0 + 4 * tid);
            const float4 a1 = *reinterpret_cast<const float4*>(imgc + r1 + 4 * tid);
            float4 v;
            v.x = a0.x * omwy + a1.x * wy;
            v.y = a0.y * omwy + a1.y * wy;
            v.z = a0.z * omwy + a1.z * wy;
            v.w = a0.w * omwy + a1.w * wy;
            *reinterpret_cast<float4*>(&buf[4 * tid]) = v;
        }

        // identity pixels (coalesced float4)
        float4 idv = make_float4(0.f, 0.f, 0.f, 0.f);
        if (tid < QW)
            idv = *reinterpret_cast<const float4*>(imgc + (size_t)y * W_ + x_base);

        __syncthreads();        // one barrier per row (double-buffered smem)

        if (tid < QW) {
            float4 o;
            o.x = idv.x * 0.6f + 0.4f * (buf[fxa[0]] * (1.0f - wxv[0]) + buf[fxb[0]] * wxv[0]);
            o.y = idv.y * 0.6f + 0.4f * (buf[fxa[1]] * (1.0f - wxv[1]) + buf[fxb[1]] * wxv[1]);
            o.z = idv.z * 0.6f + 0.4f * (buf[fxa[2]] * (1.0f - wxv[2]) + buf[fxb[2]] * wxv[2]);
            o.w = idv.w * 0.6f + 0.4f * (buf[fxa[3]] * (1.0f - wxv[3]) + buf[fxb[3]] * wxv[3]);
            *reinterpret_cast<float4*>(outc + (size_t)y * W_ + x_base) = o;
        }
    }
}

// ---------------------------------------------------------------------------
extern "C" void kernel_launch(void* const* d_in, const int* in_sizes, int n_in,
                              void* d_out, int out_size) {
    const float* images = (const float*)d_in[0];
    const float* atten  = (const float*)d_in[1];
    float* out = (float*)d_out;

    bbox_kernel<<<dim3(ROW_TILES, B_), 256>>>(atten);

    cudaLaunchConfig_t cfg = {};
    cfg.gridDim  = dim3(B_ * C_ * NGROUPS);     // 1536 blocks = single wave
    cfg.blockDim = dim3(128);
    cfg.dynamicSmemBytes = 0;
    cfg.stream = 0;
    cudaLaunchAttribute attrs[1];
    attrs[0].id = cudaLaunchAttributeProgrammaticStreamSerialization;
    attrs[0].val.programmaticStreamSerializationAllowed = 1;
    cfg.attrs = attrs;
    cfg.numAttrs = 1;
    cudaLaunchKernelEx(&cfg, blend_kernel, images, out);
}

// round 12
// speedup vs baseline: 1.0716x; 1.0043x over previous
#include <cuda_runtime.h>
#include <math.h>

#define B_  32
#define C_  3
#define H_  480
#define W_  480
#define AH  30
#define AW  30
#define PAD 48          // int(0.1 * 480)

#define ROW_TILES 30
#define ROWS_PER_TILE 16

#define BROWS 30        // rows per blend block -> 16 groups -> 1536 blocks
#define NGROUPS (H_ / BROWS)
#define XPW 120         // output columns per warp (4 warps x 120 = 480)

// Encoded bbox accumulators, zero-init == "empty mask" defaults.
// [0] = H - minh, [1] = maxh + 1, [2] = W - minw, [3] = maxw + 1.
// atomicMax-combined -> idempotent across graph replays.
__device__ int g_enc[B_][4];

// ---------------------------------------------------------------------------
// Kernel A: theta + mask tile + bbox atomics. grid=(ROW_TILES, B_), 256 thr.
// ---------------------------------------------------------------------------
__global__ void __launch_bounds__(256) bbox_kernel(const float* __restrict__ atten) {
    const int b    = blockIdx.y;
    const int tile = blockIdx.x;
    const int tid  = threadIdx.x;

    __shared__ float s_att[AH * AW];
    __shared__ float s_wmax[8];
    __shared__ int s_minh, s_maxh, s_minw, s_maxw;

    const float* a = atten + b * (AH * AW);
    float m = -1e30f;
    for (int i = tid; i < AH * AW; i += 256) {
        float v = a[i];
        s_att[i] = v;
        m = fmaxf(m, v);
    }
#pragma unroll
    for (int s = 16; s > 0; s >>= 1)
        m = fmaxf(m, __shfl_xor_sync(0xffffffffu, m, s));
    if ((tid & 31) == 0) s_wmax[tid >> 5] = m;
    if (tid == 0) { s_minh = H_; s_maxh = -1; s_minw = W_; s_maxw = -1; }
    __syncthreads();
    float mm = fmaxf(fmaxf(fmaxf(s_wmax[0], s_wmax[1]), fmaxf(s_wmax[2], s_wmax[3])),
                     fmaxf(fmaxf(s_wmax[4], s_wmax[5]), fmaxf(s_wmax[6], s_wmax[7])));
    const float theta = 0.5f * mm;

    int minh = H_, maxh = -1, minw = W_, maxw = -1;

    const int h_start = tile * ROWS_PER_TILE;
#pragma unroll 1
    for (int h = h_start; h < h_start + ROWS_PER_TILE; ++h) {
        float sy = (h + 0.5f) * 0.0625f - 0.5f;
        sy = fminf(fmaxf(sy, 0.0f), (float)(AH - 1));
        const int   y0 = (int)sy;
        const float wy = sy - (float)y0;
        const int   y1 = min(y0 + 1, AH - 1);
        const float* r0p = s_att + y0 * AW;
        const float* r1p = s_att + y1 * AW;

#pragma unroll 1
        for (int w = tid; w < W_; w += 256) {
            float sx = (w + 0.5f) * 0.0625f - 0.5f;
            sx = fminf(fmaxf(sx, 0.0f), (float)(AW - 1));
            const int   x0 = (int)sx;
            const float wx = sx - (float)x0;
            const int   x1 = min(x0 + 1, AW - 1);

            const float ra = r0p[x0] * (1.0f - wy) + r1p[x0] * wy;
            const float rb = r0p[x1] * (1.0f - wy) + r1p[x1] * wy;
            const float up = ra * (1.0f - wx) + rb * wx;

            if (up >= theta) {
                minh = min(minh, h); maxh = max(maxh, h);
                minw = min(minw, w); maxw = max(maxw, w);
            }
        }
    }

    atomicMin(&s_minh, minh); atomicMax(&s_maxh, maxh);
    atomicMin(&s_minw, minw); atomicMax(&s_maxw, maxw);
    __syncthreads();

    if (tid == 0 && s_maxh >= 0) {
        atomicMax(&g_enc[b][0], H_ - s_minh);
        atomicMax(&g_enc[b][1], s_maxh + 1);
        atomicMax(&g_enc[b][2], W_ - s_minw);
        atomicMax(&g_enc[b][3], s_maxw + 1);
    }

    asm volatile("griddepcontrol.launch_dependents;" ::: "memory");
}

// ---------------------------------------------------------------------------
// Kernel B: warp-autonomous crop-resize + blend. Each warp owns 120 output
// columns and its own smem segment; NO block barriers in the row loop.
// ---------------------------------------------------------------------------
__global__ void __launch_bounds__(128, 12) blend_kernel(const float* __restrict__ images,
                                                        float* __restrict__ out) {
    const int blk = blockIdx.x;                 // (b, c, rowgroup)
    const int b   = blk / (C_ * NGROUPS);
    const int rem = blk - b * (C_ * NGROUPS);
    const int c   = rem / NGROUPS;
    const int y_base = (rem - c * NGROUPS) * BROWS;
    const int warp = threadIdx.x >> 5;
    const int lane = threadIdx.x & 31;

    __shared__ __align__(16) float s_buf[4][128];   // per-warp source segment

    asm volatile("griddepcontrol.wait;" ::: "memory");

    // decode + pad + clamp bbox (once per block)
    const int minh = H_ - g_enc[b][0];
    const int maxh = g_enc[b][1] - 1;
    const int minw = W_ - g_enc[b][2];
    const int maxw = g_enc[b][3] - 1;
    const int h0 = max(minh - PAD, 0);
    const int h1 = min(maxh + PAD, H_);
    const int w0 = max(minw - PAD, 0);
    const int w1 = min(maxw + PAD, W_);

    const int   crop_h = h1 - h0;
    const int   crop_w = w1 - w0;
    const float chf = (float)crop_h;
    const float cwf = (float)crop_w;
    const float sy_scale = chf * (1.0f / (float)H_);
    const float sx_scale = cwf * (1.0f / (float)W_);

    // ---- per-warp source window: covers all gathers of x in [xw, xw+120) ----
    const int xw = XPW * warp;
    float sx_lo = fminf(fmaxf(((float)xw + 0.5f) * sx_scale - 0.5f, 0.0f), cwf - 1.0f);
    float sx_hi = fminf(fmaxf(((float)xw + 119.5f) * sx_scale - 0.5f, 0.0f), cwf - 1.0f);
    const int fx_lo = (int)sx_lo;
    const int fx_hi = min((int)sx_hi + 1, crop_w - 1);
    const int alo   = (w0 + fx_lo) & ~3;                 // aligned window start
    const int aend  = ((w0 + fx_hi) & ~3) + 4;           // aligned end, <= 480
    const int nqw   = (aend - alo) >> 2;                 // <= 32 quads

    // ---- per-lane x-mapping (lanes 0..29), indices relative to alo ----
    int   ia[4], ib[4];
    float wxv[4];
    const int x_base = xw + lane * 4;
    if (lane < XPW / 4) {
#pragma unroll
        for (int k = 0; k < 4; ++k) {
            float sx = ((float)(x_base + k) + 0.5f) * sx_scale - 0.5f;
            sx = fminf(fmaxf(sx, 0.0f), cwf - 1.0f);
            const int fx0 = (int)sx;
            wxv[k] = sx - (float)fx0;
            ia[k] = w0 + fx0 - alo;
            ib[k] = w0 + min(fx0 + 1, crop_w - 1) - alo;
        }
    }

    const float* __restrict__ imgc = images + ((size_t)(b * C_ + c)) * (H_ * W_);
    float* __restrict__ outc       = out    + ((size_t)(b * C_ + c)) * (H_ * W_);
    float* __restrict__ buf        = s_buf[warp];

#pragma unroll 1
    for (int r = 0; r < BROWS; ++r) {
        const int y = y_base + r;

        // y mapping (uniform across warp)
        float sy = ((float)y + 0.5f) * sy_scale - 0.5f;
        sy = fminf(fmaxf(sy, 0.0f), chf - 1.0f);
        const int   fy0  = (int)sy;
        const float wy   = sy - (float)fy0;
        const float omwy = 1.0f - wy;
        const size_t r0  = (size_t)(h0 + fy0) * W_;
        const size_t r1  = (size_t)(h0 + min(fy0 + 1, crop_h - 1)) * W_;

        // fill this warp's source segment (one quad per lane)
        if (lane < nqw) {
            const int col = alo + 4 * lane;
            const float4 a0 = *reinterpret_cast<const float4*>(imgc + r0 + col);
            const float4 a1 = *reinterpret_cast<const float4*>(imgc + r1 + col);
            float4 v;
            v.x = a0.x * omwy + a1.x * wy;
            v.y = a0.y * omwy + a1.y * wy;
            v.z = a0.z * omwy + a1.z * wy;
            v.w = a0.w * omwy + a1.w * wy;
            *reinterpret_cast<float4*>(&buf[4 * lane]) = v;
        }

        // identity pixels for this warp's segment
        float4 idv = make_float4(0.f, 0.f, 0.f, 0.f);
        if (lane < XPW / 4)
            idv = *reinterpret_cast<const float4*>(imgc + (size_t)y * W_ + x_base);

        __syncwarp();           // fill visible to this warp only

        if (lane < XPW / 4) {
            float4 o;
            o.x = idv.x * 0.6f + 0.4f * (buf[ia[0]] * (1.0f - wxv[0]) + buf[ib[0]] * wxv[0]);
            o.y = idv.y * 0.6f + 0.4f * (buf[ia[1]] * (1.0f - wxv[1]) + buf[ib[1]] * wxv[1]);
            o.z = idv.z * 0.6f + 0.4f * (buf[ia[2]] * (1.0f - wxv[2]) + buf[ib[2]] * wxv[2]);
            o.w = idv.w * 0.6f + 0.4f * (buf[ia[3]] * (1.0f - wxv[3]) + buf[ib[3]] * wxv[3]);
            *reinterpret_cast<float4*>(outc + (size_t)y * W_ + x_base) = o;
        }

        __syncwarp();           // protect buf before next row's fill
    }
}

// ---------------------------------------------------------------------------
extern "C" void kernel_launch(void* const* d_in, const int* in_sizes, int n_in,
                              void* d_out, int out_size) {
    const float* images = (const float*)d_in[0];
    const float* atten  = (const float*)d_in[1];
    float* out = (float*)d_out;

    bbox_kernel<<<dim3(ROW_TILES, B_), 256>>>(atten);

    cudaLaunchConfig_t cfg = {};
    cfg.gridDim  = dim3(B_ * C_ * NGROUPS);     // 1536 blocks, 12/SM resident
    cfg.blockDim = dim3(128);
    cfg.dynamicSmemBytes = 0;
    cfg.stream = 0;
    cudaLaunchAttribute attrs[1];
    attrs[0].id = cudaLaunchAttributeProgrammaticStreamSerialization;
    attrs[0].val.programmaticStreamSerializationAllowed = 1;
    cfg.attrs = attrs;
    cfg.numAttrs = 1;
    cudaLaunchKernelEx(&cfg, blend_kernel, images, out);
}